// round 14
// baseline (speedup 1.0000x reference)
#include <cuda_runtime.h>
#include <cuda_bf16.h>
#include <cstdint>
#include <cfloat>

// Problem constants
#define NPTS 32768   // candidate points per side
#define MQ   8192    // query (shortcut) points per side
#define CF   256     // feature channels

// Grid constants
#define G     64
#define G3    (G * G * G)          // 262144 cells per side
#define HCELL 0.125f
#define INVH  8.0f
#define ORI   (-4.0f)
#define CAP   16                   // points per cell bin
#define OVMAX 4096                 // cell overflow list capacity per side
#define RBOX  2                    // phase-1 box radius (5x5x5 = 125 cells)

// Radius-band constants (phase 2)
#define NRB     64
#define RBWF    0.1f
#define INVRBW  10.0f
#define RCAP    2560               // points per radius bin
#define ROVMAX  2048               // radius spill capacity per side

// ---------------- scratch ----------------
__device__ int    g_cnt[2 * G3];                 // per-cell counts (2 MB)
__device__ float4 g_bin[2 * G3 * CAP];           // cell-binned points (134 MB)
__device__ int    g_ovn[2];                      // cell overflow counts
__device__ float4 g_ov[2][OVMAX];                // cell overflow points
__device__ int    g_rcnt[2][NRB];                // radius-bin counts
__device__ float4 g_rbin[2][NRB][RCAP];          // radius-binned points (5.2 MB)
__device__ int    g_rovn[2];                     // radius spill counts
__device__ float4 g_rov[2][ROVMAX];              // radius spill points
__device__ int    g_idx2[2][MQ];                 // 2nd-NN index per query
__device__ int    g_failn;                       // unresolved query count
__device__ int    g_fail[2 * MQ];                // unresolved (side<<16 | q)

// ---------------- helpers ----------------
__device__ __forceinline__ int cell_of(float v) {
    int c = (int)floorf((v - ORI) * INVH);
    return min(max(c, 0), G - 1);
}

__device__ __forceinline__ int rbin_of(float rho) {
    int b = (int)(rho * INVRBW);
    return min(b, NRB - 1);
}

struct Top2 {
    float d1, d2;
    int   i1, i2;
};

__device__ __forceinline__ void t2_ins(Top2& t, float d, int j) {
    bool a = d < t.d1;
    bool b = d < t.d2;
    t.i2 = a ? t.i1 : (b ? j : t.i2);
    t.d2 = a ? t.d1 : (b ? d : t.d2);
    t.i1 = a ? j : t.i1;
    t.d1 = a ? d : t.d1;
}

__device__ __forceinline__ void t2_merge(Top2& a, const Top2& b) {
    t2_ins(a, b.d1, b.i1);
    t2_ins(a, b.d2, b.i2);
}

__device__ __forceinline__ Top2 warp_merge(Top2 t) {
    #pragma unroll
    for (int off = 16; off; off >>= 1) {
        float od1 = __shfl_xor_sync(0xffffffffu, t.d1, off);
        int   oi1 = __shfl_xor_sync(0xffffffffu, t.i1, off);
        float od2 = __shfl_xor_sync(0xffffffffu, t.d2, off);
        int   oi2 = __shfl_xor_sync(0xffffffffu, t.i2, off);
        t2_ins(t, od1, oi1);
        t2_ins(t, od2, oi2);
    }
    return t;
}

// ---------------- K0: zero counts ----------------
__global__ void zero_kernel() {
    int gid = blockIdx.x * blockDim.x + threadIdx.x;
    if (gid < 2 * G3) g_cnt[gid] = 0;
    if (gid < 2 * NRB) ((int*)g_rcnt)[gid] = 0;
    if (gid < 2) { g_ovn[gid] = 0; g_rovn[gid] = 0; }
    if (gid == 0) g_failn = 0;
}

// ---------------- K1: scatter into cell bins + radius bins ----------------
// 512-thread blocks; radius-bin histogram aggregated in smem, one bulk
// global atomic per (block, bin) to kill counter contention.
__global__ __launch_bounds__(512)
void scatter_kernel(const float* __restrict__ src_coords,
                    const float* __restrict__ tgt_coords) {
    __shared__ int scnt[NRB];
    __shared__ int sbase[NRB];

    int u = blockIdx.x * 512 + threadIdx.x;          // 0 .. 2*NPTS-1
    int side = u >> 15;                              // constant per block
    int i = u & (NPTS - 1);
    const float* c = side ? tgt_coords : src_coords;
    float x = c[3 * i], y = c[3 * i + 1], z = c[3 * i + 2];
    float4 p = make_float4(x, y, z, __int_as_float(i));

    // cell bin (phase 1) — 262144 cells, negligible contention
    int cell = side * G3 + (cell_of(z) * G + cell_of(y)) * G + cell_of(x);
    int slot = atomicAdd(&g_cnt[cell], 1);
    if (slot < CAP) {
        g_bin[cell * CAP + slot] = p;
    } else {
        int o = atomicAdd(&g_ovn[side], 1);
        if (o < OVMAX) g_ov[side][o] = p;
    }

    // radius bin (phase 2) — smem aggregation
    if (threadIdx.x < NRB) scnt[threadIdx.x] = 0;
    __syncthreads();
    float rho = sqrtf(fmaf(x, x, fmaf(y, y, z * z)));
    int rb = rbin_of(rho);
    int myrank = atomicAdd(&scnt[rb], 1);
    __syncthreads();
    if (threadIdx.x < NRB) {
        int n = scnt[threadIdx.x];
        sbase[threadIdx.x] = n ? atomicAdd(&g_rcnt[side][threadIdx.x], n) : 0;
    }
    __syncthreads();
    int rs = sbase[rb] + myrank;
    if (rs < RCAP) {
        g_rbin[side][rb][rs] = p;
    } else {
        int o = atomicAdd(&g_rovn[side], 1);
        if (o < ROVMAX) g_rov[side][o] = p;
    }
}

// ---------------- K2: phase-1 warp-per-query, fixed r=2 box ----------------
__global__ __launch_bounds__(256)
void search1_kernel(const float* __restrict__ src_sc,
                    const float* __restrict__ tgt_sc) {
    int wid = (blockIdx.x * blockDim.x + threadIdx.x) >> 5;
    int lane = threadIdx.x & 31;
    if (wid >= 2 * MQ) return;
    int side = wid >> 13;
    int q = wid & (MQ - 1);
    const float* sc = side ? tgt_sc : src_sc;
    float qx = sc[3 * q], qy = sc[3 * q + 1], qz = sc[3 * q + 2];
    int cx = cell_of(qx), cy = cell_of(qy), cz = cell_of(qz);
    int sbase = side * G3;

    Top2 t;
    t.d1 = FLT_MAX; t.d2 = FLT_MAX; t.i1 = -1; t.i2 = -1;

    const int S = 2 * RBOX + 1;            // 5
    const int TOT = S * S * S;             // 125
    for (int c = lane; c < TOT; c += 32) {
        int dz = c / (S * S);
        int rem = c - dz * (S * S);
        int dy = rem / S;
        int dx = rem - dy * S;
        int x = cx + dx - RBOX, y = cy + dy - RBOX, z = cz + dz - RBOX;
        if ((unsigned)x >= G || (unsigned)y >= G || (unsigned)z >= G) continue;
        int cell = sbase + (z * G + y) * G + x;
        int n = min(g_cnt[cell], CAP);
        int base = cell * CAP;
        for (int k = 0; k < n; k++) {
            float4 p = g_bin[base + k];
            float ddx = qx - p.x, ddy = qy - p.y, ddz = qz - p.z;
            float d = fmaf(ddx, ddx, fmaf(ddy, ddy, ddz * ddz));
            t2_ins(t, d, __float_as_int(p.w));
        }
    }
    // cell overflow points (never duplicated in bins)
    int ovn = min(g_ovn[side], OVMAX);
    for (int o = lane; o < ovn; o += 32) {
        float4 p = g_ov[side][o];
        float ddx = qx - p.x, ddy = qy - p.y, ddz = qz - p.z;
        float d = fmaf(ddx, ddx, fmaf(ddy, ddy, ddz * ddz));
        t2_ins(t, d, __float_as_int(p.w));
    }

    Top2 m = warp_merge(t);
    const float bnd2 = (RBOX * HCELL) * (RBOX * HCELL);   // 0.0625
    if (m.d2 <= bnd2) {
        if (lane == 0) g_idx2[side][q] = m.i2;
    } else if (lane == 0) {
        int o = atomicAdd(&g_failn, 1);
        g_fail[o] = (side << 16) | q;
    }
}

// ---------------- K3: phase-2 d2-targeted radial-window scan ----------------
// Block-per-item. Scan bins [b0-3, b0+3], reduce; then jump the window
// DIRECTLY to the certificate-required range [bin(rq-sqrt(d2)), bin(rq+sqrt(d2))].
// d2 only shrinks, so this converges in <=3 reduces with near-minimal scans.
// Exactness: any unscanned p has dist >= |rho_p - rq| >= sqrt(d2).
__global__ __launch_bounds__(256)
void search2_kernel(const float* __restrict__ src_sc,
                    const float* __restrict__ tgt_sc) {
    __shared__ Top2 part[8];
    __shared__ float s_d2;
    __shared__ int   s_i2;
    __shared__ int   scnt_s[NRB];
    int tid = threadIdx.x;
    int warp = tid >> 5;
    int lane = tid & 31;
    int nf = g_failn;

    for (int item = blockIdx.x; item < nf; item += gridDim.x) {
        int packed = g_fail[item];
        int side = packed >> 16;
        int q = packed & 0xffff;
        const float* sc = side ? tgt_sc : src_sc;
        float qx = sc[3 * q], qy = sc[3 * q + 1], qz = sc[3 * q + 2];
        float rq = sqrtf(fmaf(qx, qx, fmaf(qy, qy, qz * qz)));

        // preload this side's bin counts into smem (one round trip)
        if (tid < NRB) scnt_s[tid] = min(g_rcnt[side][tid], RCAP);
        __syncthreads();

        Top2 t;
        t.d1 = FLT_MAX; t.d2 = FLT_MAX; t.i1 = -1; t.i2 = -1;

        // radius spill points (disjoint from radius bins)
        int rovn = min(g_rovn[side], ROVMAX);
        for (int o = tid; o < rovn; o += 256) {
            float4 p = g_rov[side][o];
            float ddx = qx - p.x, ddy = qy - p.y, ddz = qz - p.z;
            float d = fmaf(ddx, ddx, fmaf(ddy, ddy, ddz * ddz));
            t2_ins(t, d, __float_as_int(p.w));
        }

        int b0 = rbin_of(rq);
        int lo = max(b0 - 3, 0), hi = min(b0 + 3, NRB - 1);

        // initial window scan
        for (int b = lo; b <= hi; b++) {
            int n = scnt_s[b];
            const float4* bin = g_rbin[side][b];
            for (int i = tid; i < n; i += 256) {
                float4 p = __ldg(&bin[i]);
                float ddx = qx - p.x, ddy = qy - p.y, ddz = qz - p.z;
                float d = fmaf(ddx, ddx, fmaf(ddy, ddy, ddz * ddz));
                t2_ins(t, d, __float_as_int(p.w));
            }
        }

        for (;;) {
            // two-level reduce: warp butterfly, then warp-0 butterfly over 8 partials
            Top2 w = warp_merge(t);
            if (lane == 0) part[warp] = w;
            __syncthreads();
            if (warp == 0) {
                Top2 m;
                if (lane < 8) m = part[lane];
                else { m.d1 = FLT_MAX; m.d2 = FLT_MAX; m.i1 = -1; m.i2 = -1; }
                m = warp_merge(m);
                if (lane == 0) { s_d2 = m.d2; s_i2 = m.i2; }
            }
            __syncthreads();
            float d2 = s_d2;

            // certificate-required window
            int blo, bhi;
            if (d2 < FLT_MAX) {
                float D = sqrtf(d2);
                blo = max((int)((rq - D) * INVRBW), 0);      // trunc toward 0 is safe (>= floor)
                float vhi = (rq + D) * INVRBW;
                bhi = min((int)vhi, NRB - 1);
                blo = min(blo, NRB - 1);
            } else {
                blo = max(lo - 8, 0);                        // rare: nothing found yet
                bhi = min(hi + 8, NRB - 1);
            }

            if (blo >= lo && bhi <= hi) {
                if (tid == 0) g_idx2[side][q] = s_i2;
                break;
            }
            int nlo = min(lo, blo), nhi = max(hi, bhi);
            for (int b = nlo; b < lo; b++) {
                int n = scnt_s[b];
                const float4* bin = g_rbin[side][b];
                for (int i = tid; i < n; i += 256) {
                    float4 p = __ldg(&bin[i]);
                    float ddx = qx - p.x, ddy = qy - p.y, ddz = qz - p.z;
                    float d = fmaf(ddx, ddx, fmaf(ddy, ddy, ddz * ddz));
                    t2_ins(t, d, __float_as_int(p.w));
                }
            }
            for (int b = hi + 1; b <= nhi; b++) {
                int n = scnt_s[b];
                const float4* bin = g_rbin[side][b];
                for (int i = tid; i < n; i += 256) {
                    float4 p = __ldg(&bin[i]);
                    float ddx = qx - p.x, ddy = qy - p.y, ddz = qz - p.z;
                    float d = fmaf(ddx, ddx, fmaf(ddy, ddy, ddz * ddz));
                    t2_ins(t, d, __float_as_int(p.w));
                }
            }
            lo = nlo; hi = nhi;
            __syncthreads();
        }
        __syncthreads();     // protect scnt_s reuse across items
    }
}

// ---------------- K4: gather features ----------------
// 256 threads per block, 4 rows per block (64 threads = 1 KB row of float4s).
__global__ __launch_bounds__(256)
void gather_kernel(const float* __restrict__ src_feat,
                   const float* __restrict__ tgt_feat,
                   float* __restrict__ out) {
    int row = blockIdx.x * 4 + (threadIdx.x >> 6);   // 0 .. 2*MQ-1
    int col = threadIdx.x & 63;
    int side = (row >= MQ) ? 1 : 0;
    int q = side ? (row - MQ) : row;
    const float* f = side ? tgt_feat : src_feat;
    int idx = g_idx2[side][q];
    const float4* srcp = (const float4*)(f + (size_t)idx * CF);
    float4* dstp = (float4*)(out + (size_t)row * CF);
    dstp[col] = __ldg(&srcp[col]);
}

extern "C" void kernel_launch(void* const* d_in, const int* in_sizes, int n_in,
                              void* d_out, int out_size) {
    const float* src        = (const float*)d_in[0];   // [N, C]
    const float* tgt        = (const float*)d_in[1];   // [N, C]
    const float* src_coords = (const float*)d_in[2];   // [N, 3]
    const float* tgt_coords = (const float*)d_in[3];   // [N, 3]
    const float* src_sc     = (const float*)d_in[4];   // [M, 3]
    const float* tgt_sc     = (const float*)d_in[5];   // [M, 3]
    float* out = (float*)d_out;                        // [2*M, C]

    zero_kernel<<<(2 * G3 + 255) / 256, 256>>>();
    scatter_kernel<<<2 * NPTS / 512, 512>>>(src_coords, tgt_coords);
    search1_kernel<<<(2 * MQ * 32 + 255) / 256, 256>>>(src_sc, tgt_sc);
    search2_kernel<<<2048, 256>>>(src_sc, tgt_sc);
    gather_kernel<<<2 * MQ / 4, 256>>>(src, tgt, out);
}

// round 15
// speedup vs baseline: 1.3082x; 1.3082x over previous
#include <cuda_runtime.h>
#include <cuda_bf16.h>
#include <cstdint>
#include <cfloat>

// Problem constants
#define NPTS 32768   // candidate points per side
#define MQ   8192    // query (shortcut) points per side
#define CF   256     // feature channels

// Grid constants
#define G     64
#define G3    (G * G * G)          // 262144 cells per side
#define HCELL 0.125f
#define INVH  8.0f
#define ORI   (-4.0f)
#define CAP   16                   // points per cell bin
#define OVMAX 4096                 // cell overflow list capacity per side
#define RBOX  2                    // phase-1 box radius (5x5x5 = 125 cells)

// Phase-2 split
#define CHUNKS  4
#define CHSZ    (NPTS / CHUNKS)    // 8192 points per chunk

// ---------------- scratch ----------------
__device__ int    g_cnt[2 * G3];                 // per-cell counts (2 MB)
__device__ float4 g_bin[2 * G3 * CAP];           // cell-binned points (134 MB)
__device__ int    g_ovn[2];                      // cell overflow counts
__device__ float4 g_ov[2][OVMAX];                // cell overflow points
__device__ float4 g_pts4[2][NPTS];               // packed points for phase-2
__device__ int    g_idx2[2][MQ];                 // 2nd-NN index per query
__device__ int    g_failn;                       // unresolved query count
__device__ int    g_fail[2 * MQ];                // unresolved (side<<16 | q)
__device__ float4 g_part[2 * MQ][CHUNKS];        // per-(item,chunk) Top2 partials

// ---------------- helpers ----------------
__device__ __forceinline__ int cell_of(float v) {
    int c = (int)floorf((v - ORI) * INVH);
    return min(max(c, 0), G - 1);
}

struct Top2 {
    float d1, d2;
    int   i1, i2;
};

__device__ __forceinline__ void t2_ins(Top2& t, float d, int j) {
    bool a = d < t.d1;
    bool b = d < t.d2;
    t.i2 = a ? t.i1 : (b ? j : t.i2);
    t.d2 = a ? t.d1 : (b ? d : t.d2);
    t.i1 = a ? j : t.i1;
    t.d1 = a ? d : t.d1;
}

__device__ __forceinline__ void t2_merge(Top2& a, const Top2& b) {
    t2_ins(a, b.d1, b.i1);
    t2_ins(a, b.d2, b.i2);
}

__device__ __forceinline__ Top2 warp_merge(Top2 t) {
    #pragma unroll
    for (int off = 16; off; off >>= 1) {
        float od1 = __shfl_xor_sync(0xffffffffu, t.d1, off);
        int   oi1 = __shfl_xor_sync(0xffffffffu, t.i1, off);
        float od2 = __shfl_xor_sync(0xffffffffu, t.d2, off);
        int   oi2 = __shfl_xor_sync(0xffffffffu, t.i2, off);
        t2_ins(t, od1, oi1);
        t2_ins(t, od2, oi2);
    }
    return t;
}

// ---------------- K0: zero counts ----------------
__global__ void zero_kernel() {
    int gid = blockIdx.x * blockDim.x + threadIdx.x;
    if (gid < 2 * G3) g_cnt[gid] = 0;
    if (gid < 2) g_ovn[gid] = 0;
    if (gid == 0) g_failn = 0;
}

// ---------------- K1: scatter into cell bins + packed array ----------------
__global__ void scatter_kernel(const float* __restrict__ src_coords,
                               const float* __restrict__ tgt_coords) {
    int u = blockIdx.x * blockDim.x + threadIdx.x;
    if (u >= 2 * NPTS) return;
    int side = u >> 15;
    int i = u & (NPTS - 1);
    const float* c = side ? tgt_coords : src_coords;
    float x = c[3 * i], y = c[3 * i + 1], z = c[3 * i + 2];
    float4 p = make_float4(x, y, z, __int_as_float(i));
    g_pts4[side][i] = p;
    int cell = side * G3 + (cell_of(z) * G + cell_of(y)) * G + cell_of(x);
    int slot = atomicAdd(&g_cnt[cell], 1);
    if (slot < CAP) {
        g_bin[cell * CAP + slot] = p;
    } else {
        int o = atomicAdd(&g_ovn[side], 1);
        if (o < OVMAX) g_ov[side][o] = p;
    }
}

// ---------------- K2: phase-1 warp-per-query, fixed r=2 box ----------------
__global__ __launch_bounds__(256)
void search1_kernel(const float* __restrict__ src_sc,
                    const float* __restrict__ tgt_sc) {
    int wid = (blockIdx.x * blockDim.x + threadIdx.x) >> 5;
    int lane = threadIdx.x & 31;
    if (wid >= 2 * MQ) return;
    int side = wid >> 13;
    int q = wid & (MQ - 1);
    const float* sc = side ? tgt_sc : src_sc;
    float qx = sc[3 * q], qy = sc[3 * q + 1], qz = sc[3 * q + 2];
    int cx = cell_of(qx), cy = cell_of(qy), cz = cell_of(qz);
    int sbase = side * G3;

    Top2 t;
    t.d1 = FLT_MAX; t.d2 = FLT_MAX; t.i1 = -1; t.i2 = -1;

    const int S = 2 * RBOX + 1;            // 5
    const int TOT = S * S * S;             // 125
    for (int c = lane; c < TOT; c += 32) {
        int dz = c / (S * S);
        int rem = c - dz * (S * S);
        int dy = rem / S;
        int dx = rem - dy * S;
        int x = cx + dx - RBOX, y = cy + dy - RBOX, z = cz + dz - RBOX;
        if ((unsigned)x >= G || (unsigned)y >= G || (unsigned)z >= G) continue;
        int cell = sbase + (z * G + y) * G + x;
        int n = min(g_cnt[cell], CAP);
        int base = cell * CAP;
        for (int k = 0; k < n; k++) {
            float4 p = g_bin[base + k];
            float ddx = qx - p.x, ddy = qy - p.y, ddz = qz - p.z;
            float d = fmaf(ddx, ddx, fmaf(ddy, ddy, ddz * ddz));
            t2_ins(t, d, __float_as_int(p.w));
        }
    }
    // cell overflow points (never duplicated in bins)
    int ovn = min(g_ovn[side], OVMAX);
    for (int o = lane; o < ovn; o += 32) {
        float4 p = g_ov[side][o];
        float ddx = qx - p.x, ddy = qy - p.y, ddz = qz - p.z;
        float d = fmaf(ddx, ddx, fmaf(ddy, ddy, ddz * ddz));
        t2_ins(t, d, __float_as_int(p.w));
    }

    Top2 m = warp_merge(t);
    const float bnd2 = (RBOX * HCELL) * (RBOX * HCELL);   // 0.0625
    if (m.d2 <= bnd2) {
        if (lane == 0) g_idx2[side][q] = m.i2;
    } else if (lane == 0) {
        int o = atomicAdd(&g_failn, 1);
        g_fail[o] = (side << 16) | q;
    }
}

// ---------------- K3a: phase-2 chunked brute force (partials) ----------------
// pair = item * CHUNKS + chunk. 256 threads scan this chunk's 8192 points:
// 32 evals/thread in 2 independent accumulator streams, block-reduce to one
// Top2 partial at g_part[item][chunk]. Uniform, bounded, no pruning needed.
__global__ __launch_bounds__(256)
void search2a_kernel(const float* __restrict__ src_sc,
                     const float* __restrict__ tgt_sc) {
    __shared__ Top2 part[8];
    int tid = threadIdx.x;
    int warp = tid >> 5;
    int lane = tid & 31;
    int npairs = g_failn * CHUNKS;

    for (int pair = blockIdx.x; pair < npairs; pair += gridDim.x) {
        int item = pair >> 2;              // CHUNKS = 4
        int chunk = pair & (CHUNKS - 1);
        int packed = g_fail[item];
        int side = packed >> 16;
        int q = packed & 0xffff;
        const float* sc = side ? tgt_sc : src_sc;
        float qx = sc[3 * q], qy = sc[3 * q + 1], qz = sc[3 * q + 2];
        const float4* pts = g_pts4[side] + chunk * CHSZ;

        Top2 t0, t1;
        t0.d1 = FLT_MAX; t0.d2 = FLT_MAX; t0.i1 = -1; t0.i2 = -1;
        t1 = t0;

        #pragma unroll 4
        for (int base = 0; base < CHSZ; base += 512) {
            int i0 = base + tid;
            float4 p0 = __ldg(&pts[i0]);
            float4 p1 = __ldg(&pts[i0 + 256]);
            float dx0 = qx - p0.x, dy0 = qy - p0.y, dz0 = qz - p0.z;
            float dx1 = qx - p1.x, dy1 = qy - p1.y, dz1 = qz - p1.z;
            float d0 = fmaf(dx0, dx0, fmaf(dy0, dy0, dz0 * dz0));
            float d1 = fmaf(dx1, dx1, fmaf(dy1, dy1, dz1 * dz1));
            t2_ins(t0, d0, __float_as_int(p0.w));
            t2_ins(t1, d1, __float_as_int(p1.w));
        }
        t2_merge(t0, t1);

        Top2 w = warp_merge(t0);
        if (lane == 0) part[warp] = w;
        __syncthreads();
        if (warp == 0) {
            Top2 m;
            if (lane < 8) m = part[lane];
            else { m.d1 = FLT_MAX; m.d2 = FLT_MAX; m.i1 = -1; m.i2 = -1; }
            m = warp_merge(m);
            if (lane == 0) {
                g_part[item][chunk] = make_float4(
                    m.d1, m.d2, __int_as_float(m.i1), __int_as_float(m.i2));
            }
        }
        __syncthreads();
    }
}

// ---------------- K3b: phase-2 merge partials ----------------
// Warp per item: lanes 0-3 load the 4 chunk partials, butterfly-merge.
__global__ __launch_bounds__(256)
void search2b_kernel() {
    int wid = (blockIdx.x * blockDim.x + threadIdx.x) >> 5;
    int lane = threadIdx.x & 31;
    int nwarps = (gridDim.x * blockDim.x) >> 5;
    int nf = g_failn;

    for (int item = wid; item < nf; item += nwarps) {
        Top2 t;
        if (lane < CHUNKS) {
            float4 v = g_part[item][lane];
            t.d1 = v.x; t.d2 = v.y;
            t.i1 = __float_as_int(v.z); t.i2 = __float_as_int(v.w);
        } else {
            t.d1 = FLT_MAX; t.d2 = FLT_MAX; t.i1 = -1; t.i2 = -1;
        }
        Top2 m = warp_merge(t);
        if (lane == 0) {
            int packed = g_fail[item];
            int side = packed >> 16;
            int q = packed & 0xffff;
            g_idx2[side][q] = m.i2;
        }
    }
}

// ---------------- K4: gather features ----------------
// 256 threads per block, 4 rows per block (64 threads = 1 KB row of float4s).
__global__ __launch_bounds__(256)
void gather_kernel(const float* __restrict__ src_feat,
                   const float* __restrict__ tgt_feat,
                   float* __restrict__ out) {
    int row = blockIdx.x * 4 + (threadIdx.x >> 6);   // 0 .. 2*MQ-1
    int col = threadIdx.x & 63;
    int side = (row >= MQ) ? 1 : 0;
    int q = side ? (row - MQ) : row;
    const float* f = side ? tgt_feat : src_feat;
    int idx = g_idx2[side][q];
    const float4* srcp = (const float4*)(f + (size_t)idx * CF);
    float4* dstp = (float4*)(out + (size_t)row * CF);
    dstp[col] = __ldg(&srcp[col]);
}

extern "C" void kernel_launch(void* const* d_in, const int* in_sizes, int n_in,
                              void* d_out, int out_size) {
    const float* src        = (const float*)d_in[0];   // [N, C]
    const float* tgt        = (const float*)d_in[1];   // [N, C]
    const float* src_coords = (const float*)d_in[2];   // [N, 3]
    const float* tgt_coords = (const float*)d_in[3];   // [N, 3]
    const float* src_sc     = (const float*)d_in[4];   // [M, 3]
    const float* tgt_sc     = (const float*)d_in[5];   // [M, 3]
    float* out = (float*)d_out;                        // [2*M, C]

    zero_kernel<<<(2 * G3 + 255) / 256, 256>>>();
    scatter_kernel<<<(2 * NPTS + 255) / 256, 256>>>(src_coords, tgt_coords);
    search1_kernel<<<(2 * MQ * 32 + 255) / 256, 256>>>(src_sc, tgt_sc);
    search2a_kernel<<<4096, 256>>>(src_sc, tgt_sc);
    search2b_kernel<<<64, 256>>>();
    gather_kernel<<<2 * MQ / 4, 256>>>(src, tgt, out);
}

// round 16
// speedup vs baseline: 1.3103x; 1.0016x over previous
#include <cuda_runtime.h>
#include <cuda_bf16.h>
#include <cstdint>
#include <cfloat>

// Problem constants
#define NPTS 32768   // candidate points per side
#define MQ   8192    // query (shortcut) points per side
#define CF   256     // feature channels

// Fine grid (phase 1)
#define G     64
#define G3    (G * G * G)          // 262144 cells per side
#define HCELL 0.125f
#define INVH  8.0f
#define ORI   (-4.0f)
#define CAP   16                   // points per fine cell bin
#define OVMAX 4096                 // fine overflow capacity per side
#define RBOX  2                    // phase-1 box radius (5x5x5 = 125 cells)

// Coarse grid (escalation)
#define G2     16
#define G2_3   (G2 * G2 * G2)      // 4096 cells per side
#define H2     0.5f
#define INVH2  2.0f
#define CAP2   512                 // points per coarse cell
#define OV2MAX 2048                // coarse spill capacity per side

// ---------------- scratch ----------------
__device__ int    g_cnt[2 * G3];                 // fine cell counts (2 MB)
__device__ float4 g_bin[2 * G3 * CAP];           // fine-binned points (134 MB)
__device__ int    g_ovn[2];                      // fine overflow counts
__device__ float4 g_ov[2][OVMAX];                // fine overflow points
__device__ int    g_cnt2[2 * G2_3];              // coarse cell counts (32 KB)
__device__ float4 g_bin2[2 * G2_3 * CAP2];       // coarse-binned points (64 MB)
__device__ int    g_ov2n[2];                     // coarse spill counts
__device__ float4 g_ov2[2][OV2MAX];              // coarse spill points
__device__ int    g_idx2[2][MQ];                 // 2nd-NN index per query

// ---------------- helpers ----------------
__device__ __forceinline__ int cell_of(float v) {
    int c = (int)floorf((v - ORI) * INVH);
    return min(max(c, 0), G - 1);
}
__device__ __forceinline__ int cell2_of(float v) {
    int c = (int)floorf((v - ORI) * INVH2);
    return min(max(c, 0), G2 - 1);
}

struct Top2 {
    float d1, d2;
    int   i1, i2;
};

__device__ __forceinline__ void t2_ins(Top2& t, float d, int j) {
    bool a = d < t.d1;
    bool b = d < t.d2;
    t.i2 = a ? t.i1 : (b ? j : t.i2);
    t.d2 = a ? t.d1 : (b ? d : t.d2);
    t.i1 = a ? j : t.i1;
    t.d1 = a ? d : t.d1;
}

__device__ __forceinline__ Top2 warp_merge(Top2 t) {
    #pragma unroll
    for (int off = 16; off; off >>= 1) {
        float od1 = __shfl_xor_sync(0xffffffffu, t.d1, off);
        int   oi1 = __shfl_xor_sync(0xffffffffu, t.i1, off);
        float od2 = __shfl_xor_sync(0xffffffffu, t.d2, off);
        int   oi2 = __shfl_xor_sync(0xffffffffu, t.i2, off);
        t2_ins(t, od1, oi1);
        t2_ins(t, od2, oi2);
    }
    return t;
}

// ---------------- K0: zero counts ----------------
__global__ void zero_kernel() {
    int gid = blockIdx.x * blockDim.x + threadIdx.x;
    if (gid < 2 * G3) g_cnt[gid] = 0;
    if (gid < 2 * G2_3) g_cnt2[gid] = 0;
    if (gid < 2) { g_ovn[gid] = 0; g_ov2n[gid] = 0; }
}

// ---------------- K1: scatter into fine + coarse bins ----------------
__global__ void scatter_kernel(const float* __restrict__ src_coords,
                               const float* __restrict__ tgt_coords) {
    int u = blockIdx.x * blockDim.x + threadIdx.x;
    if (u >= 2 * NPTS) return;
    int side = u >> 15;
    int i = u & (NPTS - 1);
    const float* c = side ? tgt_coords : src_coords;
    float x = c[3 * i], y = c[3 * i + 1], z = c[3 * i + 2];
    float4 p = make_float4(x, y, z, __int_as_float(i));

    // fine bin
    int cell = side * G3 + (cell_of(z) * G + cell_of(y)) * G + cell_of(x);
    int slot = atomicAdd(&g_cnt[cell], 1);
    if (slot < CAP) {
        g_bin[cell * CAP + slot] = p;
    } else {
        int o = atomicAdd(&g_ovn[side], 1);
        if (o < OVMAX) g_ov[side][o] = p;
    }

    // coarse bin
    int cell2 = side * G2_3 + (cell2_of(z) * G2 + cell2_of(y)) * G2 + cell2_of(x);
    int slot2 = atomicAdd(&g_cnt2[cell2], 1);
    if (slot2 < CAP2) {
        g_bin2[cell2 * CAP2 + slot2] = p;
    } else {
        int o = atomicAdd(&g_ov2n[side], 1);
        if (o < OV2MAX) g_ov2[side][o] = p;
    }
}

// ---------------- K2: warp-per-query search (fine box + coarse escalation) ----------------
__global__ __launch_bounds__(256)
void search_kernel(const float* __restrict__ src_sc,
                   const float* __restrict__ tgt_sc) {
    int wid = (blockIdx.x * blockDim.x + threadIdx.x) >> 5;
    int lane = threadIdx.x & 31;
    if (wid >= 2 * MQ) return;
    int side = wid >> 13;
    int q = wid & (MQ - 1);
    const float* sc = side ? tgt_sc : src_sc;
    float qx = sc[3 * q], qy = sc[3 * q + 1], qz = sc[3 * q + 2];
    int cx = cell_of(qx), cy = cell_of(qy), cz = cell_of(qz);
    int sbase = side * G3;

    // ---- phase 1: fine r=2 box ----
    Top2 t;
    t.d1 = FLT_MAX; t.d2 = FLT_MAX; t.i1 = -1; t.i2 = -1;

    const int S = 2 * RBOX + 1;            // 5
    const int TOT = S * S * S;             // 125
    for (int c = lane; c < TOT; c += 32) {
        int dz = c / (S * S);
        int rem = c - dz * (S * S);
        int dy = rem / S;
        int dx = rem - dy * S;
        int x = cx + dx - RBOX, y = cy + dy - RBOX, z = cz + dz - RBOX;
        if ((unsigned)x >= G || (unsigned)y >= G || (unsigned)z >= G) continue;
        int cell = sbase + (z * G + y) * G + x;
        int n = min(g_cnt[cell], CAP);
        int base = cell * CAP;
        for (int k = 0; k < n; k++) {
            float4 p = g_bin[base + k];
            float ddx = qx - p.x, ddy = qy - p.y, ddz = qz - p.z;
            float d = fmaf(ddx, ddx, fmaf(ddy, ddy, ddz * ddz));
            t2_ins(t, d, __float_as_int(p.w));
        }
    }
    int ovn = min(g_ovn[side], OVMAX);
    for (int o = lane; o < ovn; o += 32) {
        float4 p = g_ov[side][o];
        float ddx = qx - p.x, ddy = qy - p.y, ddz = qz - p.z;
        float d = fmaf(ddx, ddx, fmaf(ddy, ddy, ddz * ddz));
        t2_ins(t, d, __float_as_int(p.w));
    }

    Top2 m = warp_merge(t);
    const float bnd2 = (RBOX * HCELL) * (RBOX * HCELL);   // 0.0625
    if (m.d2 <= bnd2) {
        if (lane == 0) g_idx2[side][q] = m.i2;
        return;
    }

    // ---- phase 2: coarse-box escalation (warp-cooperative) ----
    int c2x = cell2_of(qx), c2y = cell2_of(qy), c2z = cell2_of(qz);
    int sbase2 = side * G2_3;
    int ov2n = min(g_ov2n[side], OV2MAX);

    for (int r2 = 1; ; r2++) {
        t.d1 = FLT_MAX; t.d2 = FLT_MAX; t.i1 = -1; t.i2 = -1;   // re-init (dup-safe)

        int xlo = max(c2x - r2, 0), xhi = min(c2x + r2, G2 - 1);
        int ylo = max(c2y - r2, 0), yhi = min(c2y + r2, G2 - 1);
        int zlo = max(c2z - r2, 0), zhi = min(c2z + r2, G2 - 1);
        int nx = xhi - xlo + 1, ny = yhi - ylo + 1, nz = zhi - zlo + 1;
        int total = nx * ny * nz;

        for (int base_c = 0; base_c < total; base_c += 32) {
            int cidx = base_c + lane;
            int mycell = -1, myn = 0;
            if (cidx < total) {
                int z = cidx / (nx * ny);
                int rem = cidx - z * (nx * ny);
                int y = rem / nx;
                int x = rem - y * nx;
                mycell = sbase2 + ((z + zlo) * G2 + (y + ylo)) * G2 + (x + xlo);
                myn = min(g_cnt2[mycell], CAP2);
            }
            unsigned mask = __ballot_sync(0xffffffffu, myn > 0);
            while (mask) {
                int b = __ffs(mask) - 1;
                mask &= mask - 1;
                int cell_b = __shfl_sync(0xffffffffu, mycell, b);
                int n_b    = __shfl_sync(0xffffffffu, myn, b);
                int pbase = cell_b * CAP2;
                for (int k = lane; k < n_b; k += 32) {
                    float4 p = __ldg(&g_bin2[pbase + k]);
                    float ddx = qx - p.x, ddy = qy - p.y, ddz = qz - p.z;
                    float d = fmaf(ddx, ddx, fmaf(ddy, ddy, ddz * ddz));
                    t2_ins(t, d, __float_as_int(p.w));
                }
            }
        }
        // coarse spill points (disjoint from coarse bins)
        for (int o = lane; o < ov2n; o += 32) {
            float4 p = g_ov2[side][o];
            float ddx = qx - p.x, ddy = qy - p.y, ddz = qz - p.z;
            float d = fmaf(ddx, ddx, fmaf(ddy, ddy, ddz * ddz));
            t2_ins(t, d, __float_as_int(p.w));
        }

        m = warp_merge(t);
        float bound = (float)r2 * H2;
        bool full = (xlo == 0 && ylo == 0 && zlo == 0 &&
                     xhi == G2 - 1 && yhi == G2 - 1 && zhi == G2 - 1);
        if (bound * bound >= m.d2 || full) {
            if (lane == 0) g_idx2[side][q] = m.i2;
            return;
        }
    }
}

// ---------------- K3: gather features ----------------
// 256 threads per block, 4 rows per block (64 threads = 1 KB row of float4s).
__global__ __launch_bounds__(256)
void gather_kernel(const float* __restrict__ src_feat,
                   const float* __restrict__ tgt_feat,
                   float* __restrict__ out) {
    int row = blockIdx.x * 4 + (threadIdx.x >> 6);   // 0 .. 2*MQ-1
    int col = threadIdx.x & 63;
    int side = (row >= MQ) ? 1 : 0;
    int q = side ? (row - MQ) : row;
    const float* f = side ? tgt_feat : src_feat;
    int idx = g_idx2[side][q];
    const float4* srcp = (const float4*)(f + (size_t)idx * CF);
    float4* dstp = (float4*)(out + (size_t)row * CF);
    dstp[col] = __ldg(&srcp[col]);
}

extern "C" void kernel_launch(void* const* d_in, const int* in_sizes, int n_in,
                              void* d_out, int out_size) {
    const float* src        = (const float*)d_in[0];   // [N, C]
    const float* tgt        = (const float*)d_in[1];   // [N, C]
    const float* src_coords = (const float*)d_in[2];   // [N, 3]
    const float* tgt_coords = (const float*)d_in[3];   // [N, 3]
    const float* src_sc     = (const float*)d_in[4];   // [M, 3]
    const float* tgt_sc     = (const float*)d_in[5];   // [M, 3]
    float* out = (float*)d_out;                        // [2*M, C]

    zero_kernel<<<(2 * G3 + 255) / 256, 256>>>();
    scatter_kernel<<<(2 * NPTS + 255) / 256, 256>>>(src_coords, tgt_coords);
    search_kernel<<<(2 * MQ * 32 + 255) / 256, 256>>>(src_sc, tgt_sc);
    gather_kernel<<<2 * MQ / 4, 256>>>(src, tgt, out);
}